// round 1
// baseline (speedup 1.0000x reference)
#include <cuda_runtime.h>
#include <math.h>

#define BB 32
#define TT 1024
#define DD 512
#define KK 64
#define OO 1024
#define F_EPS 1e-12f

// Scratch (device globals — no allocation allowed)
__device__ float g_a[BB * TT * KK];      // soft-assign [B,T,K]  (8 MB)
__device__ float g_agg[BB * KK * DD];    // x_agg, then normalized v in-place (4 MB)
__device__ float g_sumw[BB * KK];        // per-(b,k) soft weight sums
__device__ float g_norm2[BB];            // per-b squared norm after intra-norm

// ---------------------------------------------------------------------------
// K1: logits = x @ W + bias, softmax over K, write a, accumulate sum_w.
// Tile: 64 rows x 64 centers per block, 256 threads, 4x4 register tile.
// ---------------------------------------------------------------------------
__global__ __launch_bounds__(256) void k_assign(const float* __restrict__ x,
                                                const float* __restrict__ w,
                                                const float* __restrict__ bias) {
    __shared__ __align__(16) float xs[64 * 65];
    __shared__ __align__(16) float ws[64 * 64];
    __shared__ float bias_s[64];
    __shared__ float ssum[64];

    const int tid = threadIdx.x;
    const int r0 = blockIdx.x * 64;           // global row base (b*T + t)
    const int kg = tid & 15;                  // k-group
    const int rg = tid >> 4;                  // row-group
    const int k4 = kg * 4;
    const int r4 = rg * 4;

    if (tid < 64) { ssum[tid] = 0.0f; bias_s[tid] = bias[tid]; }

    float acc[4][4];
#pragma unroll
    for (int i = 0; i < 4; i++)
#pragma unroll
        for (int j = 0; j < 4; j++) acc[i][j] = 0.0f;

    for (int d0 = 0; d0 < DD; d0 += 64) {
        // load x tile [64 rows x 64 d] (padded stride 65)
#pragma unroll
        for (int i = 0; i < 4; i++) {
            int idx = tid + i * 256;          // float4 index 0..1023
            int row = idx >> 4;
            int dc  = (idx & 15) * 4;
            float4 v = *(const float4*)&x[(size_t)(r0 + row) * DD + d0 + dc];
            xs[row * 65 + dc + 0] = v.x;
            xs[row * 65 + dc + 1] = v.y;
            xs[row * 65 + dc + 2] = v.z;
            xs[row * 65 + dc + 3] = v.w;
        }
        // load W tile: 4096 contiguous floats at w + d0*64
#pragma unroll
        for (int i = 0; i < 4; i++) {
            int idx = tid + i * 256;
            *(float4*)&ws[idx * 4] = *(const float4*)&w[(size_t)d0 * KK + idx * 4];
        }
        __syncthreads();

#pragma unroll 4
        for (int d = 0; d < 64; d++) {
            float4 wv = *(float4*)&ws[d * 64 + k4];
            float xv[4];
#pragma unroll
            for (int i = 0; i < 4; i++) xv[i] = xs[(r4 + i) * 65 + d];
#pragma unroll
            for (int i = 0; i < 4; i++) {
                acc[i][0] = fmaf(xv[i], wv.x, acc[i][0]);
                acc[i][1] = fmaf(xv[i], wv.y, acc[i][1]);
                acc[i][2] = fmaf(xv[i], wv.z, acc[i][2]);
                acc[i][3] = fmaf(xv[i], wv.w, acc[i][3]);
            }
        }
        __syncthreads();
    }

    // softmax per row: 64 logits live on 16 consecutive lanes (same rg half)
    float colsum[4] = {0.f, 0.f, 0.f, 0.f};
#pragma unroll
    for (int i = 0; i < 4; i++) {
        float v[4];
        float m = -1e30f;
#pragma unroll
        for (int j = 0; j < 4; j++) {
            v[j] = acc[i][j] + bias_s[k4 + j];
            m = fmaxf(m, v[j]);
        }
#pragma unroll
        for (int off = 8; off > 0; off >>= 1)
            m = fmaxf(m, __shfl_xor_sync(0xffffffffu, m, off));
        float s = 0.0f;
#pragma unroll
        for (int j = 0; j < 4; j++) { v[j] = __expf(v[j] - m); s += v[j]; }
#pragma unroll
        for (int off = 8; off > 0; off >>= 1)
            s += __shfl_xor_sync(0xffffffffu, s, off);
        float inv = 1.0f / s;
        float4 av;
        av.x = v[0] * inv; av.y = v[1] * inv; av.z = v[2] * inv; av.w = v[3] * inv;
        colsum[0] += av.x; colsum[1] += av.y; colsum[2] += av.z; colsum[3] += av.w;
        *(float4*)&g_a[(size_t)(r0 + r4 + i) * KK + k4] = av;
    }

    // per-block sum_w reduction then one global atomic per k
#pragma unroll
    for (int j = 0; j < 4; j++) atomicAdd(&ssum[k4 + j], colsum[j]);
    __syncthreads();
    if (tid < 64) atomicAdd(&g_sumw[(r0 >> 10) * KK + tid], ssum[tid]);
}

// ---------------------------------------------------------------------------
// K2: x_agg[b,k,d] = sum_t a[b,t,k] * x[b,t,d]
// grid: b(32) x dtile(4 of 128) x tseg(4 of 256) = 512 blocks, 128 threads.
// Each thread owns one d, accumulates all 64 k in registers, REDG epilogue.
// ---------------------------------------------------------------------------
__global__ __launch_bounds__(128) void k_agg(const float* __restrict__ x) {
    __shared__ __align__(16) float as[16 * 64];
    const int tid = threadIdx.x;
    const int bx = blockIdx.x;
    const int b   = bx >> 4;
    const int dt  = (bx >> 2) & 3;
    const int seg = bx & 3;
    const int d   = dt * 128 + tid;
    const int t0  = seg * 256;

    float acc[64];
#pragma unroll
    for (int k = 0; k < 64; k++) acc[k] = 0.0f;

    for (int tt0 = 0; tt0 < 256; tt0 += 16) {
        // load a[b, t0+tt0 .. +16, :] = 1024 contiguous floats
#pragma unroll
        for (int i = 0; i < 2; i++) {
            int idx = tid + i * 128;          // float4 index 0..255
            *(float4*)&as[idx * 4] =
                *(const float4*)&g_a[(size_t)(b * TT + t0 + tt0) * KK + idx * 4];
        }
        __syncthreads();
#pragma unroll 2
        for (int tt = 0; tt < 16; tt++) {
            float xv = x[(size_t)(b * TT + t0 + tt0 + tt) * DD + d];
#pragma unroll
            for (int kk = 0; kk < 16; kk++) {
                float4 av = *(float4*)&as[tt * 64 + kk * 4];
                acc[kk * 4 + 0] = fmaf(av.x, xv, acc[kk * 4 + 0]);
                acc[kk * 4 + 1] = fmaf(av.y, xv, acc[kk * 4 + 1]);
                acc[kk * 4 + 2] = fmaf(av.z, xv, acc[kk * 4 + 2]);
                acc[kk * 4 + 3] = fmaf(av.w, xv, acc[kk * 4 + 3]);
            }
        }
        __syncthreads();
    }
#pragma unroll
    for (int k = 0; k < 64; k++)
        atomicAdd(&g_agg[((size_t)b * KK + k) * DD + d], acc[k]);
}

// ---------------------------------------------------------------------------
// K3: residual vs centers + intra L2-normalize per (b,k); accumulate per-b
// squared norm of the normalized vector for the second normalization.
// ---------------------------------------------------------------------------
__global__ __launch_bounds__(128) void k_norm(const float* __restrict__ centers) {
    const int bx = blockIdx.x;                // 2048 = B*K
    const int b = bx >> 6;
    const int k = bx & 63;
    const int tid = threadIdx.x;

    const float sw = g_sumw[b * KK + k];
    const size_t base = ((size_t)b * KK + k) * DD;

    float4 xa = *(float4*)&g_agg[base + tid * 4];
    float4 c  = *(const float4*)&centers[(size_t)k * DD + tid * 4];
    float4 f;
    f.x = xa.x - sw * c.x;
    f.y = xa.y - sw * c.y;
    f.z = xa.z - sw * c.z;
    f.w = xa.w - sw * c.w;
    float ss = f.x * f.x + f.y * f.y + f.z * f.z + f.w * f.w;

#pragma unroll
    for (int off = 16; off > 0; off >>= 1)
        ss += __shfl_xor_sync(0xffffffffu, ss, off);

    __shared__ float wsum[4];
    __shared__ float scale_s;
    if ((tid & 31) == 0) wsum[tid >> 5] = ss;
    __syncthreads();
    if (tid == 0) {
        float tot = wsum[0] + wsum[1] + wsum[2] + wsum[3];
        float sc = rsqrtf(fmaxf(tot, F_EPS));
        scale_s = sc;
        atomicAdd(&g_norm2[b], tot * sc * sc);
    }
    __syncthreads();
    float sc = scale_s;
    f.x *= sc; f.y *= sc; f.z *= sc; f.w *= sc;
    *(float4*)&g_agg[base + tid * 4] = f;   // in-place: g_agg now holds v
}

// ---------------------------------------------------------------------------
// K4: out[b,o] += sum_kd v[b,kd] * R[kd,o]
// grid: 8 o-tiles(128) x 16 kd-chunks(2048) = 128 blocks, 256 threads.
// Thread tile: 4 b x 4 o. Accumulate into d_out via REDG (pre-zeroed).
// ---------------------------------------------------------------------------
__global__ __launch_bounds__(256) void k_out(const float* __restrict__ R,
                                             float* __restrict__ out) {
    __shared__ __align__(16) float vs[64 * 36];     // [kd_local][b], pad 36
    __shared__ __align__(16) float rs[64 * 132];    // [kd_local][o_local], pad 132

    const int tid = threadIdx.x;
    const int bx = blockIdx.x;
    const int o0  = (bx & 7) * 128;
    const int kd0 = (bx >> 3) * 2048;
    const int bq = tid & 7;        // b = bq*4 + i
    const int oq = tid >> 3;       // o = o0 + oq*4 + j

    float acc[4][4];
#pragma unroll
    for (int i = 0; i < 4; i++)
#pragma unroll
        for (int j = 0; j < 4; j++) acc[i][j] = 0.0f;

    for (int c0 = 0; c0 < 2048; c0 += 64) {
        // load v chunk: [64 kd x 32 b] transposed into smem
        {
            int bl  = tid & 31;
            int kdl = (tid >> 5) * 8;
            const float* src = &g_agg[(size_t)bl * (KK * DD) + kd0 + c0 + kdl];
            float4 v0 = *(const float4*)src;
            float4 v1 = *(const float4*)(src + 4);
            float tmp[8] = {v0.x, v0.y, v0.z, v0.w, v1.x, v1.y, v1.z, v1.w};
#pragma unroll
            for (int m = 0; m < 8; m++) vs[(kdl + m) * 36 + bl] = tmp[m];
        }
        // load R chunk: [64 kd x 128 o]
#pragma unroll
        for (int p = 0; p < 2; p++) {
            int row  = (tid >> 3) + p * 32;
            int colb = (tid & 7) * 4;
            const float* src = &R[(size_t)(kd0 + c0 + row) * OO + o0];
#pragma unroll
            for (int q = 0; q < 4; q++) {
                int col = colb + q * 32;
                *(float4*)&rs[row * 132 + col] = *(const float4*)&src[col];
            }
        }
        __syncthreads();

#pragma unroll 8
        for (int kd = 0; kd < 64; kd++) {
            float4 vv = *(float4*)&vs[kd * 36 + bq * 4];
            float4 rv = *(float4*)&rs[kd * 132 + oq * 4];
            acc[0][0] = fmaf(vv.x, rv.x, acc[0][0]);
            acc[0][1] = fmaf(vv.x, rv.y, acc[0][1]);
            acc[0][2] = fmaf(vv.x, rv.z, acc[0][2]);
            acc[0][3] = fmaf(vv.x, rv.w, acc[0][3]);
            acc[1][0] = fmaf(vv.y, rv.x, acc[1][0]);
            acc[1][1] = fmaf(vv.y, rv.y, acc[1][1]);
            acc[1][2] = fmaf(vv.y, rv.z, acc[1][2]);
            acc[1][3] = fmaf(vv.y, rv.w, acc[1][3]);
            acc[2][0] = fmaf(vv.z, rv.x, acc[2][0]);
            acc[2][1] = fmaf(vv.z, rv.y, acc[2][1]);
            acc[2][2] = fmaf(vv.z, rv.z, acc[2][2]);
            acc[2][3] = fmaf(vv.z, rv.w, acc[2][3]);
            acc[3][0] = fmaf(vv.w, rv.x, acc[3][0]);
            acc[3][1] = fmaf(vv.w, rv.y, acc[3][1]);
            acc[3][2] = fmaf(vv.w, rv.z, acc[3][2]);
            acc[3][3] = fmaf(vv.w, rv.w, acc[3][3]);
        }
        __syncthreads();
    }

#pragma unroll
    for (int i = 0; i < 4; i++)
#pragma unroll
        for (int j = 0; j < 4; j++)
            atomicAdd(&out[(size_t)(bq * 4 + i) * OO + o0 + oq * 4 + j], acc[i][j]);
}

// ---------------------------------------------------------------------------
// K5: apply second L2-normalize scale (linear, folded after GEMM)
// ---------------------------------------------------------------------------
__global__ __launch_bounds__(256) void k_finish(float* __restrict__ out) {
    int i = blockIdx.x * 256 + threadIdx.x;   // 32768 = B*O
    int b = i >> 10;
    out[i] *= rsqrtf(fmaxf(g_norm2[b], F_EPS));
}

extern "C" void kernel_launch(void* const* d_in, const int* in_sizes, int n_in,
                              void* d_out, int out_size) {
    const float* x       = (const float*)d_in[0];
    const float* w       = (const float*)d_in[1];
    const float* bias    = (const float*)d_in[2];
    const float* centers = (const float*)d_in[3];
    const float* R       = (const float*)d_in[4];
    float* out = (float*)d_out;

    void *p_agg, *p_sumw, *p_norm2;
    cudaGetSymbolAddress(&p_agg, g_agg);
    cudaGetSymbolAddress(&p_sumw, g_sumw);
    cudaGetSymbolAddress(&p_norm2, g_norm2);

    cudaMemsetAsync(p_agg, 0, sizeof(float) * BB * KK * DD);
    cudaMemsetAsync(p_sumw, 0, sizeof(float) * BB * KK);
    cudaMemsetAsync(p_norm2, 0, sizeof(float) * BB);
    cudaMemsetAsync(d_out, 0, sizeof(float) * BB * OO);

    k_assign<<<512, 256>>>(x, w, bias);
    k_agg<<<512, 128>>>(x);
    k_norm<<<2048, 128>>>(centers);
    k_out<<<128, 256>>>(R, out);
    k_finish<<<128, 256>>>(out);
}